// round 16
// baseline (speedup 1.0000x reference)
#include <cuda_runtime.h>
#include <cuda_bf16.h>
#include <math.h>
#include <stdint.h>

// ---------------------------------------------------------------------------
// KAN layer as one concatenated GEMM (mma.sync bf16 — measured-best path).
// K layout (KTOT=7168): [0,512) silu_hi*w_hi, [512,1024) silu_lo*w_hi,
// [1024,1536) silu_hi*w_lo, [1536,7168): k=1536+kk*512+i spline*(w*c)
// NEW: stream-K GEMM over 148 CTAs (was 128; 20 SMs idle). Work space =
// 32 tiles x 56 k-iters = 1792 units, balanced integer partition; each CTA
// covers <=2 segments, writes full-tile partials to closed-form slots;
// reduce sums the per-tile slots in fixed deterministic order.
// prep_a/prep_b fork-join on streams (measured win) kept.
// ---------------------------------------------------------------------------

#define BATCH 1024
#define NIN   512
#define NOUT  512
#define NB    11
#define KSIL  1536
#define KTOT  7168

#define BM 128
#define BN 128
#define BK 128
#define KITERS  (KTOT / BK)        // 56
#define TILES_N (NOUT / BN)        // 4
#define NTILES  ((BATCH / BM) * TILES_N)   // 32
#define UNITS   (NTILES * KITERS)  // 1792
#define NCTA    148
#define MAXSEG  8
#define TILE_ELEMS (BM * BN)       // 16384

#define STAGES 3
#define ASTAGE (BM * BK * 2)       // 32768
#define BSTAGE (BN * BK * 2)       // 32768
#define STAGE_BYTES (ASTAGE + BSTAGE)
#define SMEM_TOTAL (STAGES * STAGE_BYTES)   // 196608
#define SUBTILE 16384              // 128 rows x 64 cols bf16 (SW128 atom tile)

// Scratch (allocation-free rule: __device__ globals)
__device__ __align__(128) __nv_bfloat16 g_A [(size_t)BATCH * KTOT];
__device__ __align__(128) __nv_bfloat16 g_Bt[(size_t)NOUT  * KTOT];
__device__ __align__(128) float         g_P [(size_t)MAXSEG * NTILES * TILE_ELEMS]; // 16.8MB

// owner CTA of work-unit v under balanced partition u0(c)=floor(c*UNITS/NCTA)
__device__ __forceinline__ int owner_of(int v) {
    return ((v + 1) * NCTA - 1) / UNITS;
}

// ---------------------------------------------------------------------------
// prep_a: silu hi/lo + closed-form uniform cubic B-spline via smem scatter.
// ---------------------------------------------------------------------------
__global__ void __launch_bounds__(256) prep_a_kernel(const float* __restrict__ X) {
    __shared__ uint32_t sc[256 * NB];
    const int tid = threadIdx.x;
    int pid = blockIdx.x * 256 + tid;
    int b  = pid >> 8;
    int ip = (pid & 255) << 1;
    float2 xv = *(const float2*)(X + (size_t)b * NIN + ip);

    float s0 = xv.x / (1.0f + __expf(-xv.x));
    float s1 = xv.y / (1.0f + __expf(-xv.y));
    __nv_bfloat16 shi0 = __float2bfloat16(s0), shi1 = __float2bfloat16(s1);
    __nv_bfloat16 slo0 = __float2bfloat16(s0 - __bfloat162float(shi0));
    __nv_bfloat16 slo1 = __float2bfloat16(s1 - __bfloat162float(shi1));

    __nv_bfloat16* row = g_A + (size_t)b * KTOT;
    *(__nv_bfloat162*)(row + ip)        = __nv_bfloat162(shi0, shi1);
    *(__nv_bfloat162*)(row + 512 + ip)  = __nv_bfloat162(slo0, slo1);
    *(__nv_bfloat162*)(row + 1024 + ip) = __nv_bfloat162(shi0, shi1);

#pragma unroll
    for (int kk = 0; kk < NB; kk++) sc[tid * NB + kk] = 0;

    unsigned short* sh = (unsigned short*)sc;
#pragma unroll
    for (int j = 0; j < 2; j++) {
        float x = j ? xv.y : xv.x;
        float pos = (x + 5.25f) * (1.0f / 0.75f);
        int jc = (int)floorf(pos);
        if (jc >= 0 && jc <= 13) {
            float u  = pos - (float)jc;
            float u2 = u * u, u3 = u2 * u;
            float omu = 1.0f - u;
            float w0 = omu * omu * omu * (1.0f / 6.0f);
            float w1 = (3.0f * u3 - 6.0f * u2 + 4.0f) * (1.0f / 6.0f);
            float w2 = (-3.0f * u3 + 3.0f * u2 + 3.0f * u + 1.0f) * (1.0f / 6.0f);
            float w3 = u3 * (1.0f / 6.0f);
#pragma unroll
            for (int d = 0; d < 4; d++) {
                int m = jc - 3 + d;
                if (m >= 0 && m <= 10) {
                    float wd = (d == 0) ? w0 : (d == 1) ? w1 : (d == 2) ? w2 : w3;
                    __nv_bfloat16 h = __float2bfloat16(wd);
                    sh[(tid * NB + m) * 2 + j] = *reinterpret_cast<unsigned short*>(&h);
                }
            }
        }
    }
#pragma unroll
    for (int kk = 0; kk < NB; kk++)
        *(uint32_t*)(row + KSIL + kk * NIN + ip) = sc[tid * NB + kk];
}

__global__ void __launch_bounds__(256) prep_b_kernel(const float* __restrict__ W,
                                                     const float* __restrict__ C) {
    int pid = blockIdx.x * 256 + threadIdx.x;
    int o  = pid >> 8;
    int ip = (pid & 255) << 1;

    float w0 = W[(size_t)ip * NOUT + o];
    float w1 = W[(size_t)(ip + 1) * NOUT + o];
    __nv_bfloat16 whi0 = __float2bfloat16(w0), whi1 = __float2bfloat16(w1);
    __nv_bfloat16 wlo0 = __float2bfloat16(w0 - __bfloat162float(whi0));
    __nv_bfloat16 wlo1 = __float2bfloat16(w1 - __bfloat162float(whi1));

    __nv_bfloat16* row = g_Bt + (size_t)o * KTOT;
    *(__nv_bfloat162*)(row + ip)        = __nv_bfloat162(whi0, whi1);
    *(__nv_bfloat162*)(row + 512 + ip)  = __nv_bfloat162(whi0, whi1);
    *(__nv_bfloat162*)(row + 1024 + ip) = __nv_bfloat162(wlo0, wlo1);

    const float* c0 = C + ((size_t)ip * NOUT + o) * NB;
    const float* c1 = C + ((size_t)(ip + 1) * NOUT + o) * NB;
#pragma unroll
    for (int kk = 0; kk < NB; kk++)
        *(__nv_bfloat162*)(row + KSIL + kk * NIN + ip) =
            __nv_bfloat162(__float2bfloat16(w0 * c0[kk]),
                           __float2bfloat16(w1 * c1[kk]));
}

// ---------------------------------------------------------------------------
// GEMM helpers (per-CTA schedule identical to the measured-36us kernel)
// ---------------------------------------------------------------------------
__device__ __forceinline__ void cpa16(uint32_t dst, const void* src) {
    asm volatile("cp.async.cg.shared.global [%0], [%1], 16;\n" :: "r"(dst), "l"(src));
}

#define LDSM_X4(r, addr)                                                       \
    asm volatile("ldmatrix.sync.aligned.m8n8.x4.shared.b16 {%0,%1,%2,%3}, [%4];\n" \
                 : "=r"((r)[0]), "=r"((r)[1]), "=r"((r)[2]), "=r"((r)[3])      \
                 : "r"(addr))

#define MMA16816(d, a, b0, b1)                                                 \
    asm volatile("mma.sync.aligned.m16n8k16.row.col.f32.bf16.bf16.f32 "        \
                 "{%0,%1,%2,%3}, {%4,%5,%6,%7}, {%8,%9}, {%0,%1,%2,%3};\n"     \
                 : "+f"((d)[0]), "+f"((d)[1]), "+f"((d)[2]), "+f"((d)[3])      \
                 : "r"((a)[0]), "r"((a)[1]), "r"((a)[2]), "r"((a)[3]),         \
                   "r"(b0), "r"(b1))

// Ag/Bg already offset to (row-band, k0); kt is segment-local
__device__ __forceinline__ void load_stage(const char* Ag, const char* Bg, int kt,
                                           int tid, uint32_t smem_u32) {
    uint32_t base = smem_u32 + (kt % STAGES) * STAGE_BYTES;
    const char* Ak = Ag + (size_t)kt * (BK * 2);
#pragma unroll
    for (int it = 0; it < 8; it++) {
        int t = tid + it * 256;
        int r = t >> 4, c = t & 15;
        uint32_t dst = base + ((c >> 3) << 14) + r * 128 + (((c & 7) ^ (r & 7)) << 4);
        cpa16(dst, Ak + (size_t)r * (KTOT * 2) + (c << 4));
    }
    const char* Bk = Bg + (size_t)kt * (BK * 2);
#pragma unroll
    for (int it = 0; it < 8; it++) {
        int t = tid + it * 256;
        int r = t >> 4, c = t & 15;
        uint32_t dst = base + ASTAGE + ((c >> 3) << 14) + r * 128 + (((c & 7) ^ (r & 7)) << 4);
        cpa16(dst, Bk + (size_t)r * (KTOT * 2) + (c << 4));
    }
    asm volatile("cp.async.commit_group;\n" ::);
}

__global__ void __launch_bounds__(256, 1) kan_gemm_kernel() {
    extern __shared__ __align__(1024) char smem[];
    const uint32_t smem_u32 = (uint32_t)__cvta_generic_to_shared(smem);
    const int tid  = threadIdx.x;
    const int cta  = blockIdx.x;

    const int u0 = (cta * UNITS) / NCTA;
    const int u1 = ((cta + 1) * UNITS) / NCTA;

    const int lane = tid & 31;
    const int warp = tid >> 5;
    const int wm   = warp >> 1;   // 0..3 : 32-row band
    const int wn   = warp & 1;    // 0..1 : 64-col band
    const int lr   = lane & 15;
    const int hf   = lane >> 4;

    int u = u0;
    while (u < u1) {
        const int t  = u / KITERS;
        const int k0 = u - t * KITERS;
        const int kn = min(KITERS - k0, u1 - u);
        const int m0 = (t >> 2) * BM;           // TILES_N = 4
        const int n0 = (t & 3) * BN;

        const char* Ag = (const char*)g_A  + ((size_t)m0 * KTOT + (size_t)k0 * BK) * 2;
        const char* Bg = (const char*)g_Bt + ((size_t)n0 * KTOT + (size_t)k0 * BK) * 2;

        float acc[2][8][4];
#pragma unroll
        for (int mt = 0; mt < 2; mt++)
#pragma unroll
            for (int nt = 0; nt < 8; nt++)
#pragma unroll
                for (int e = 0; e < 4; e++) acc[mt][nt][e] = 0.0f;

        // preamble: always 3 commits (empty if past segment end)
#pragma unroll
        for (int s = 0; s < 3; s++) {
            if (s < kn) load_stage(Ag, Bg, s, tid, smem_u32);
            else        asm volatile("cp.async.commit_group;\n" ::);
        }

        for (int kt = 0; kt < kn; kt++) {
            asm volatile("cp.async.wait_group 2;\n" ::);
            __syncthreads();

            const uint32_t sbase = smem_u32 + (kt % STAGES) * STAGE_BYTES;

#pragma unroll
            for (int ks = 0; ks < 8; ks++) {
                const int sub = ks >> 2;
                const int ck  = ks & 3;
                uint32_t af[2][4], bf[4][4];
#pragma unroll
                for (int mt = 0; mt < 2; mt++) {
                    int r  = wm * 32 + mt * 16 + lr;
                    int ch = (ck * 2 + hf) ^ (r & 7);
                    LDSM_X4(af[mt], sbase + sub * SUBTILE + r * 128 + (ch << 4));
                }
#pragma unroll
                for (int p = 0; p < 4; p++) {
                    int r  = wn * 64 + p * 16 + lr;
                    int ch = (ck * 2 + hf) ^ (r & 7);
                    LDSM_X4(bf[p], sbase + ASTAGE + sub * SUBTILE + r * 128 + (ch << 4));
                }
#pragma unroll
                for (int mt = 0; mt < 2; mt++)
#pragma unroll
                    for (int p = 0; p < 4; p++)
#pragma unroll
                        for (int q = 0; q < 2; q++)
                            MMA16816(acc[mt][p * 2 + q], af[mt], bf[p][q], bf[p][q + 2]);
            }
            __syncthreads();

            if (kt + 3 < kn) load_stage(Ag, Bg, kt + 3, tid, smem_u32);
            else             asm volatile("cp.async.commit_group;\n" ::);
        }

        // epilogue: write tile-local partial to this segment's slot
        const int seg = cta - owner_of(t * KITERS);
        float* P = g_P + ((size_t)(seg * NTILES + t)) * TILE_ELEMS;
#pragma unroll
        for (int mt = 0; mt < 2; mt++)
#pragma unroll
            for (int nt = 0; nt < 8; nt++) {
                int row0 = wm * 32 + mt * 16 + (lane >> 2);
                int col  = wn * 64 + nt * 8 + (lane & 3) * 2;
                *(float2*)&P[(size_t)row0 * BN + col] =
                    make_float2(acc[mt][nt][0], acc[mt][nt][1]);
                *(float2*)&P[(size_t)(row0 + 8) * BN + col] =
                    make_float2(acc[mt][nt][2], acc[mt][nt][3]);
            }

        u += kn;
    }
}

// ---------------------------------------------------------------------------
// Deterministic fixed-order stream-K reduction: per tile, sum slots 0..nseg-1
// ---------------------------------------------------------------------------
__global__ void __launch_bounds__(256) reduce_kernel(float* __restrict__ Out) {
    int idx = blockIdx.x * 256 + threadIdx.x;       // float4 index over output
    int b  = idx >> 7;                              // NOUT/4 = 128 float4/row
    int c4 = idx & 127;
    int t  = (b >> 7) * TILES_N + (c4 >> 5);        // tile id
    int e4 = (b & 127) * (BN / 4) + (c4 & 31);      // float4 index within tile

    int cf = owner_of(t * KITERS);
    int cl = owner_of(t * KITERS + KITERS - 1);
    int nseg = cl - cf + 1;                         // 5 or 6

    const float4* P = (const float4*)g_P;
    size_t base = (size_t)t * (TILE_ELEMS / 4) + e4;
    size_t slot_stride = (size_t)NTILES * (TILE_ELEMS / 4);

    float4 r = P[base];
    for (int s = 1; s < nseg; s++) {
        float4 v = P[base + (size_t)s * slot_stride];
        r.x += v.x; r.y += v.y; r.z += v.z; r.w += v.w;
    }
    ((float4*)Out)[idx] = r;
}

// ---------------------------------------------------------------------------
extern "C" void kernel_launch(void* const* d_in, const int* in_sizes, int n_in,
                              void* d_out, int out_size) {
    const float* X = nullptr;
    const float* C = nullptr;
    const float* W = nullptr;
    for (int i = 0; i < n_in; i++) {
        if      (in_sizes[i] == BATCH * NIN)      X = (const float*)d_in[i];
        else if (in_sizes[i] == NIN * NOUT * NB)  C = (const float*)d_in[i];
        else if (in_sizes[i] == NIN * NOUT)       W = (const float*)d_in[i];
    }

    static cudaStream_t s2 = nullptr;
    static cudaEvent_t ev_fork = nullptr, ev_join = nullptr;
    if (!s2) {
        cudaStreamCreateWithFlags(&s2, cudaStreamNonBlocking);
        cudaEventCreateWithFlags(&ev_fork, cudaEventDisableTiming);
        cudaEventCreateWithFlags(&ev_join, cudaEventDisableTiming);
        cudaFuncSetAttribute(kan_gemm_kernel,
                             cudaFuncAttributeMaxDynamicSharedMemorySize, SMEM_TOTAL);
    }

    // fork: prep_b on s2, prep_a on the main stream (independent kernels)
    cudaEventRecord(ev_fork, 0);
    cudaStreamWaitEvent(s2, ev_fork, 0);
    prep_b_kernel<<<(NIN * NOUT / 2) / 256, 256, 0, s2>>>(W, C);
    cudaEventRecord(ev_join, s2);

    prep_a_kernel<<<(BATCH * NIN / 2) / 256, 256>>>(X);

    cudaStreamWaitEvent(0, ev_join, 0);

    kan_gemm_kernel<<<NCTA, 256, SMEM_TOTAL>>>();

    reduce_kernel<<<(BATCH * NOUT / 4) / 256, 256>>>((float*)d_out);
}